// round 15
// baseline (speedup 1.0000x reference)
#include <cuda_runtime.h>

#define RREL  3
#define EMBD  32
#define HIDD  64
#define NMAX  300000
#define EMAX  1500000
#define GMAX  30000

// Table sizes: combined shape-color rows (26*10=260) + pos rows (128)
#define TSC   260
#define TPOS  128
#define SC3   (3 * TSC * HIDD)           // 49920
#define PO3   (3 * TPOS * HIDD)          // 24576
#define RSC   (TSC * HIDD)               // 16640
#define RPO   (TPOS * HIDD)              // 8192

// ---------------- scratch (static device memory; no allocs) ----------------
// Self-cleaning invariant: every counter is zero at kernel_launch entry
// (static zero-init first call; re-zeroed by its last consumer each call).
__device__ float g_h1[(size_t)NMAX * HIDD];            // relu(layer1 out)
__device__ float g_agg[(size_t)NMAX * RREL * HIDD];    // per-rel aggregated relu(h1)
__device__ float g_inv[NMAX * RREL];                   // 1/max(cnt,1) per (node, rel)
__device__ int   g_cnt[NMAX * RREL];                   // zeroed by k_base
__device__ int   g_base4[NMAX * 4];                    // {s0, s1, s2, end} per node
__device__ int   g_fill[NMAX * RREL];                  // zeroed by k_agg2
__device__ int   g_gcnt[GMAX];                         // zeroed by k_agg1
__device__ float g_ginv[GMAX];
__device__ int   g_ctr[1];                             // zeroed by k_place
__device__ unsigned int g_pids[NMAX];                  // scidx | pi<<9  (16 bits)
__device__ unsigned int g_esrc[EMAX];                  // src node, rel-sorted CSR
__device__ unsigned int g_epid[EMAX];                  // pids[src], rel-sorted CSR
__device__ float g_tabSC[SC3];                         // [rel][si*10+ci][j]: (se+ce) @ W1[rel]
__device__ float g_tabPos[PO3];                        // [rel][pi][j]:      pe @ W1[rel]
__device__ float g_rootSC[RSC];                        // (se+ce) @ root1
__device__ float g_rootPos[RPO];                       // pe @ root1
__device__ float g_Btf[256 * 64];                      // [root2; W2_r] pre-rounded to tf32

__device__ __forceinline__ void red_add_v2(float* p, float a, float b) {
    asm volatile("red.global.add.v2.f32 [%0], {%1,%2};"
                 :: "l"(p), "f"(a), "f"(b) : "memory");
}

#define MMA_TF32(C, A, B) \
    asm("mma.sync.aligned.m16n8k8.row.col.f32.tf32.tf32.f32 " \
        "{%0,%1,%2,%3}, {%4,%5,%6,%7}, {%8,%9}, {%0,%1,%2,%3};" \
        : "+f"((C)[0]), "+f"((C)[1]), "+f"((C)[2]), "+f"((C)[3]) \
        : "r"((A)[0]), "r"((A)[1]), "r"((A)[2]), "r"((A)[3]), \
          "r"((B)[0]), "r"((B)[1]))

// ---------------- kernels ----------------
// Fused prep: per-(dst,rel) edge counts + packed ids + weight tables + tf32 B.
__global__ void k_prep(const int* __restrict__ ei, const int* __restrict__ et, int E,
                       const int* __restrict__ sid, const int* __restrict__ cid,
                       const int* __restrict__ pid, int N,
                       const float* __restrict__ se, const float* __restrict__ ce,
                       const float* __restrict__ pe, const float* __restrict__ W1,
                       const float* __restrict__ root1,
                       const float* __restrict__ root2, const float* __restrict__ W2) {
    int t = blockIdx.x * blockDim.x + threadIdx.x;
    if (t < E) atomicAdd(&g_cnt[ei[E + t] * RREL + et[t]], 1);
    if (t < N) g_pids[t] = (unsigned)(sid[t] * 10 + cid[t]) | ((unsigned)pid[t] << 9);
    if (t < 256 * 64) {
        int kk = t >> 6, c = t & 63;
        float w;
        if (kk < 64) w = root2[kk * HIDD + c];
        else {
            int kr = kk - 64;
            w = W2[((size_t)(kr >> 6) * HIDD + (kr & 63)) * HIDD + c];
        }
        unsigned u;
        asm("cvt.rna.tf32.f32 %0, %1;" : "=r"(u) : "f"(w));
        g_Btf[t] = __uint_as_float(u);
    }
    if (t < SC3 + PO3 + RSC + RPO) {
        if (t < SC3) {
            int rel = t / (TSC * HIDD), rem = t % (TSC * HIDD);
            int row = rem / HIDD, j = rem % HIDD;
            int si = row / 10, ci = row % 10;
            const float* w = W1 + (size_t)rel * EMBD * HIDD + j;
            float s = 0.f;
            #pragma unroll
            for (int k = 0; k < EMBD; k++)
                s += (se[si * EMBD + k] + ce[ci * EMBD + k]) * w[k * HIDD];
            g_tabSC[t] = s;
        } else if (t < SC3 + PO3) {
            int u = t - SC3;
            int rel = u / (TPOS * HIDD), rem = u % (TPOS * HIDD);
            int row = rem / HIDD, j = rem % HIDD;
            const float* w = W1 + (size_t)rel * EMBD * HIDD + j;
            float s = 0.f;
            #pragma unroll
            for (int k = 0; k < EMBD; k++) s += pe[row * EMBD + k] * w[k * HIDD];
            g_tabPos[u] = s;
        } else if (t < SC3 + PO3 + RSC) {
            int u = t - SC3 - PO3;
            int row = u / HIDD, j = u % HIDD;
            int si = row / 10, ci = row % 10;
            float s = 0.f;
            #pragma unroll
            for (int k = 0; k < EMBD; k++)
                s += (se[si * EMBD + k] + ce[ci * EMBD + k]) * root1[k * HIDD + j];
            g_rootSC[u] = s;
        } else {
            int u = t - SC3 - PO3 - RSC;
            int row = u / HIDD, j = u % HIDD;
            float s = 0.f;
            #pragma unroll
            for (int k = 0; k < EMBD; k++) s += pe[row * EMBD + k] * root1[k * HIDD + j];
            g_rootPos[u] = s;
        }
    }
}

// Per node: inv weights, graph counts, rel-sorted CSR segment boundaries.
// Re-zeroes g_cnt (self-cleaning).
__global__ void k_base(const int* __restrict__ batch, int N) {
    int t    = blockIdx.x * blockDim.x + threadIdx.x;
    int lane = threadIdx.x & 31;
    int deg  = 0, c0 = 0, c1 = 0;
    if (t < N) {
        c0 = g_cnt[3 * t]; c1 = g_cnt[3 * t + 1];
        int c2 = g_cnt[3 * t + 2];
        g_cnt[3 * t] = 0; g_cnt[3 * t + 1] = 0; g_cnt[3 * t + 2] = 0;
        deg = c0 + c1 + c2;
        g_inv[3 * t + 0] = 1.0f / (float)(c0 > 0 ? c0 : 1);
        g_inv[3 * t + 1] = 1.0f / (float)(c1 > 0 ? c1 : 1);
        g_inv[3 * t + 2] = 1.0f / (float)(c2 > 0 ? c2 : 1);
        atomicAdd(&g_gcnt[batch[t]], 1);
    }
    int incl = deg;
    #pragma unroll
    for (int off = 1; off < 32; off <<= 1) {
        int v = __shfl_up_sync(0xffffffffu, incl, off);
        if (lane >= off) incl += v;
    }
    int total = __shfl_sync(0xffffffffu, incl, 31);
    int base = 0;
    if (lane == 31 && total > 0) base = atomicAdd(&g_ctr[0], total);
    base = __shfl_sync(0xffffffffu, base, 31);
    if (t < N) {
        int b = base + incl - deg;
        int4 v; v.x = b; v.y = b + c0; v.z = b + c0 + c1; v.w = b + deg;
        *(int4*)&g_base4[4 * t] = v;
    }
}

// CSR placement into per-(dst,rel) segments; split src/pid arrays. Resets g_ctr.
__global__ void k_place(const int* __restrict__ ei, const int* __restrict__ et, int E) {
    int e = blockIdx.x * blockDim.x + threadIdx.x;
    if (e == 0) g_ctr[0] = 0;
    if (e >= E) return;
    int s = ei[e], d = ei[E + e], r = et[e];
    int pos = g_base4[4 * d + r] + atomicAdd(&g_fill[3 * d + r], 1);
    g_esrc[pos] = (unsigned)s;
    g_epid[pos] = g_pids[s];
}

// Layer 1: HALF-warp per dst node (16 lanes x float4); ONE fused loop over the
// whole adjacency, rel recovered by comparing e against segment boundaries.
// Per edge: pid (pipelined), 2 table gathers, w-weighted FMA. Merged outinit.
__global__ __launch_bounds__(256, 6) void k_agg1(
        const float* __restrict__ b1,
        const float* __restrict__ lin_b, float* __restrict__ out,
        int G, int N) {
    int gt = blockIdx.x * blockDim.x + threadIdx.x;
    if (gt < G) {
        out[2 * gt + 0] = lin_b[0];
        out[2 * gt + 1] = lin_b[1];
        int c = g_gcnt[gt];
        g_ginv[gt] = 1.0f / (float)(c > 0 ? c : 1);
        g_gcnt[gt] = 0;
    }
    int lane = threadIdx.x & 31;
    int half = lane >> 4, l = lane & 15;
    int d = blockIdx.x * 16 + (threadIdx.x >> 5) * 2 + half;
    if (d >= N) return;
    int j = l * 4;
    int4 b = *(const int4*)&g_base4[4 * d];
    float inv0 = g_inv[3 * d], inv1 = g_inv[3 * d + 1], inv2 = g_inv[3 * d + 2];
    float4 acc = {0.f, 0.f, 0.f, 0.f};
    unsigned pn = (b.x < b.w) ? g_epid[b.x] : 0u;
    for (int e = b.x; e < b.w; e++) {
        unsigned p = pn;
        if (e + 1 < b.w) pn = g_epid[e + 1];
        int rel = (e >= b.y) + (e >= b.z);
        float w = (e < b.y) ? inv0 : ((e < b.z) ? inv1 : inv2);
        int scx = p & 511, pp = (int)(p >> 9);
        float4 m0 = *(const float4*)&g_tabSC[rel * (TSC * HIDD) + scx * HIDD + j];
        float4 m1 = *(const float4*)&g_tabPos[rel * (TPOS * HIDD) + pp * HIDD + j];
        acc.x += w * (m0.x + m1.x);
        acc.y += w * (m0.y + m1.y);
        acc.z += w * (m0.z + m1.z);
        acc.w += w * (m0.w + m1.w);
    }
    unsigned pd = g_pids[d];
    int scx = pd & 511, pp = (int)(pd >> 9);
    float4 r0 = *(const float4*)&g_rootSC[scx * HIDD + j];
    float4 r1 = *(const float4*)&g_rootPos[pp * HIDD + j];
    float4 bv = *(const float4*)&b1[j];
    float4 o;
    o.x = fmaxf(acc.x + r0.x + r1.x + bv.x, 0.f);
    o.y = fmaxf(acc.y + r0.y + r1.y + bv.y, 0.f);
    o.z = fmaxf(acc.z + r0.z + r1.z + bv.z, 0.f);
    o.w = fmaxf(acc.w + r0.w + r1.w + bv.w, 0.f);
    *(float4*)&g_h1[(size_t)d * HIDD + j] = o;
}

// Layer 2 aggregation: HALF-warp per node, ONE fused loop, predicated per-rel
// accumulate. Resets g_fill (self-cleaning).
__global__ __launch_bounds__(256, 6) void k_agg2(int N) {
    int lane = threadIdx.x & 31;
    int half = lane >> 4, l = lane & 15;
    int d = blockIdx.x * 16 + (threadIdx.x >> 5) * 2 + half;
    if (d >= N) return;
    int j = l * 4;
    int4 b = *(const int4*)&g_base4[4 * d];
    if (l < 3) g_fill[3 * d + l] = 0;
    float4 s0 = {0.f, 0.f, 0.f, 0.f}, s1 = s0, s2 = s0;
    unsigned sn = (b.x < b.w) ? g_esrc[b.x] : 0u;
    for (int e = b.x; e < b.w; e++) {
        unsigned src = sn;
        if (e + 1 < b.w) sn = g_esrc[e + 1];
        float4 v = *(const float4*)&g_h1[(size_t)src * HIDD + j];
        if (e < b.y)      { s0.x += v.x; s0.y += v.y; s0.z += v.z; s0.w += v.w; }
        else if (e < b.z) { s1.x += v.x; s1.y += v.y; s1.z += v.z; s1.w += v.w; }
        else              { s2.x += v.x; s2.y += v.y; s2.z += v.z; s2.w += v.w; }
    }
    float inv0 = g_inv[3 * d], inv1 = g_inv[3 * d + 1], inv2 = g_inv[3 * d + 2];
    float* dst = g_agg + (size_t)d * (RREL * HIDD);
    float4 o0, o1, o2;
    o0.x = s0.x * inv0; o0.y = s0.y * inv0; o0.z = s0.z * inv0; o0.w = s0.w * inv0;
    o1.x = s1.x * inv1; o1.y = s1.y * inv1; o1.z = s1.z * inv1; o1.w = s1.w * inv1;
    o2.x = s2.x * inv2; o2.y = s2.y * inv2; o2.z = s2.z * inv2; o2.w = s2.w * inv2;
    *(float4*)&dst[j]             = o0;
    *(float4*)&dst[HIDD + j]      = o1;
    *(float4*)&dst[2 * HIDD + j]  = o2;
}

// Layer-2 GEMM via single tf32 mma.sync + fused pooling head.
// Per CTA: 128 nodes x 64 cols, K=256 in 8 chunks of 32. 8 warps:
//   warp tile = 32 rows x 32 cols = 2 m-frags x 4 n-frags of m16n8k8.
#define AP  36   // Ah row stride
#define BQ  72   // Bs k-row stride
#define H2P 66
#define POOLSZ (128 * H2P)   // 8448 floats; staging needs 128*AP+32*BQ = 6912
__global__ __launch_bounds__(256, 4) void k_gemm_mma(
        const float* __restrict__ b2, const float* __restrict__ linW,
        const int* __restrict__ batch, float* __restrict__ out, int N) {
    __shared__ float pool[POOLSZ];                   // 33.8 KB
    float* Ah  = pool;
    float* Bs  = pool + 128 * AP;
    float* h2s = pool;                               // overlay after K loop

    int i0  = blockIdx.x * 128;
    int tid = threadIdx.x;
    int w   = tid >> 5, lane = tid & 31;
    int g   = lane >> 2, t4 = lane & 3;
    int rowbase = (w >> 1) * 32, colbase = (w & 1) * 32;

    float c[2][4][4];
    #pragma unroll
    for (int mt = 0; mt < 2; mt++)
        #pragma unroll
        for (int nt = 0; nt < 4; nt++)
            #pragma unroll
            for (int q = 0; q < 4; q++) c[mt][nt][q] = 0.f;

    for (int ph = 0; ph < 8; ph++) {
        __syncthreads();
        // ---- stage B chunk [32 x 64] (already tf32-rounded) ----
        #pragma unroll
        for (int t = 0; t < 8; t++) {
            int idx = tid + t * 256;
            int k = idx >> 6, cc = idx & 63;
            Bs[k * BQ + cc] = g_Btf[(ph * 32 + k) * 64 + cc];
        }
        // ---- stage A chunk [128 node x 32 k], tf32-rounded ----
        {
            int node = tid & 127, half = tid >> 7;    // half covers k 0..15 / 16..31
            int gi = i0 + node;
            float4 v[4];
            if (gi < N) {
                const float4* src;
                if (ph < 2) src = (const float4*)&g_h1[(size_t)gi * HIDD + ph * 32 + half * 16];
                else        src = (const float4*)&g_agg[(size_t)gi * (RREL * HIDD) + (ph - 2) * 32 + half * 16];
                #pragma unroll
                for (int q = 0; q < 4; q++) v[q] = src[q];
            } else {
                #pragma unroll
                for (int q = 0; q < 4; q++) v[q] = make_float4(0.f, 0.f, 0.f, 0.f);
            }
            #pragma unroll
            for (int q = 0; q < 4; q++) {
                float vals[4] = {v[q].x, v[q].y, v[q].z, v[q].w};
                #pragma unroll
                for (int e = 0; e < 4; e++) {
                    unsigned hu;
                    asm("cvt.rna.tf32.f32 %0, %1;" : "=r"(hu) : "f"(vals[e]));
                    Ah[node * AP + half * 16 + q * 4 + e] = __uint_as_float(hu);
                }
            }
        }
        __syncthreads();
        // ---- 4 k-steps of 8 ----
        #pragma unroll
        for (int ks = 0; ks < 4; ks++) {
            int k0 = ks * 8;
            unsigned ah[2][4], bf[4][2];
            #pragma unroll
            for (int mt = 0; mt < 2; mt++) {
                int r0 = rowbase + 16 * mt + g;
                ah[mt][0] = __float_as_uint(Ah[r0 * AP + k0 + t4]);
                ah[mt][1] = __float_as_uint(Ah[(r0 + 8) * AP + k0 + t4]);
                ah[mt][2] = __float_as_uint(Ah[r0 * AP + k0 + t4 + 4]);
                ah[mt][3] = __float_as_uint(Ah[(r0 + 8) * AP + k0 + t4 + 4]);
            }
            #pragma unroll
            for (int nt = 0; nt < 4; nt++) {
                int cc = colbase + 8 * nt + g;
                bf[nt][0] = __float_as_uint(Bs[(k0 + t4) * BQ + cc]);
                bf[nt][1] = __float_as_uint(Bs[(k0 + t4 + 4) * BQ + cc]);
            }
            #pragma unroll
            for (int mt = 0; mt < 2; mt++)
                #pragma unroll
                for (int nt = 0; nt < 4; nt++)
                    MMA_TF32(c[mt][nt], ah[mt], bf[nt]);
        }
    }
    __syncthreads();
    // ---- store h2 tile to smem (overlay) ----
    #pragma unroll
    for (int mt = 0; mt < 2; mt++)
        #pragma unroll
        for (int nt = 0; nt < 4; nt++) {
            int r0 = rowbase + 16 * mt + g;
            int cc = colbase + 8 * nt + 2 * t4;
            *(float2*)&h2s[r0 * H2P + cc]       = make_float2(c[mt][nt][0], c[mt][nt][1]);
            *(float2*)&h2s[(r0 + 8) * H2P + cc] = make_float2(c[mt][nt][2], c[mt][nt][3]);
        }
    __syncthreads();
    // ---- per-warp row reduction: rows 16w..16w+15 ----
    float2 bb = *(const float2*)&b2[2 * lane];
    float4 lw = *(const float4*)&linW[4 * lane];   // cols 2lane, 2lane+1 x outs {0,1}
    for (int rr = 0; rr < 16; rr++) {
        int row = w * 16 + rr;
        float2 v = *(const float2*)&h2s[row * H2P + 2 * lane];
        float v0 = fmaxf(v.x + bb.x, 0.f);
        float v1 = fmaxf(v.y + bb.y, 0.f);
        float s0 = v0 * lw.x + v1 * lw.z;
        float s1 = v0 * lw.y + v1 * lw.w;
        #pragma unroll
        for (int m = 16; m > 0; m >>= 1) {
            s0 += __shfl_xor_sync(0xffffffffu, s0, m);
            s1 += __shfl_xor_sync(0xffffffffu, s1, m);
        }
        int gi = i0 + row;
        if (lane == 0 && gi < N) {
            int b = batch[gi];
            float gw = g_ginv[b];
            red_add_v2(&out[2 * b], s0 * gw, s1 * gw);
        }
    }
}

// ---------------- launch ----------------
extern "C" void kernel_launch(void* const* d_in, const int* in_sizes, int n_in,
                              void* d_out, int out_size) {
    const int* sid = (const int*)d_in[0];
    const int* cid = (const int*)d_in[1];
    const int* pid = (const int*)d_in[2];
    const int* ei  = (const int*)d_in[3];
    const int* et  = (const int*)d_in[4];
    const int* bat = (const int*)d_in[5];
    int off = (in_sizes[6] == 1) ? 7 : 6;
    const float* se    = (const float*)d_in[off + 0];
    const float* ce    = (const float*)d_in[off + 1];
    const float* pe    = (const float*)d_in[off + 2];
    const float* W1    = (const float*)d_in[off + 3];
    const float* root1 = (const float*)d_in[off + 4];
    const float* b1    = (const float*)d_in[off + 5];
    const float* W2    = (const float*)d_in[off + 6];
    const float* root2 = (const float*)d_in[off + 7];
    const float* b2    = (const float*)d_in[off + 8];
    const float* linW  = (const float*)d_in[off + 9];
    const float* linb  = (const float*)d_in[off + 10];
    float* out = (float*)d_out;

    int N = in_sizes[0];
    int E = in_sizes[4];
    int G = out_size / 2;
    const int TB = 256;

    k_prep<<<(E + TB - 1) / TB, TB>>>(ei, et, E, sid, cid, pid, N,
                                      se, ce, pe, W1, root1, root2, W2);
    k_base<<<(N + TB - 1) / TB, TB>>>(bat, N);
    k_place<<<(E + TB - 1) / TB, TB>>>(ei, et, E);
    k_agg1<<<(N + 15) / 16, TB>>>(b1, linb, out, G, N);   // <- profiled slot (4th)
    k_agg2<<<(N + 15) / 16, TB>>>(N);
    k_gemm_mma<<<(N + 127) / 128, TB>>>(b2, linW, bat, out, N);
}

// round 17
// speedup vs baseline: 1.0439x; 1.0439x over previous
#include <cuda_runtime.h>

#define RREL  3
#define EMBD  32
#define HIDD  64
#define NMAX  300000
#define EMAX  1500000
#define GMAX  30000

// Table sizes: combined shape-color rows (26*10=260) + pos rows (128)
#define TSC   260
#define TPOS  128
#define SC3   (3 * TSC * HIDD)           // 49920
#define PO3   (3 * TPOS * HIDD)          // 24576
#define RSC   (TSC * HIDD)               // 16640
#define RPO   (TPOS * HIDD)              // 8192

// ---------------- scratch (static device memory; no allocs) ----------------
// Self-cleaning invariant: every counter is zero at kernel_launch entry
// (static zero-init first call; re-zeroed by its last consumer each call).
__device__ float g_h1[(size_t)NMAX * HIDD];            // relu(layer1 out)
__device__ float g_agg[(size_t)NMAX * RREL * HIDD];    // per-rel aggregated relu(h1)
__device__ float g_inv[NMAX * RREL];                   // 1/max(cnt,1) per (node, rel)
__device__ int   g_cnt[NMAX * RREL];                   // zeroed by k_base
__device__ int   g_base4[NMAX * 4];                    // {s0, s1, s2, end} per node
__device__ int   g_fill[NMAX * RREL];                  // zeroed by k_agg2
__device__ int   g_gcnt[GMAX];                         // zeroed by k_agg1
__device__ float g_ginv[GMAX];
__device__ int   g_ctr[1];                             // zeroed by k_place
__device__ unsigned int g_pids[NMAX];                  // scidx | pi<<9  (16 bits)
__device__ unsigned long long g_edge[EMAX];            // lo: src ; hi: pids[src]
__device__ float g_tabSC[SC3];                         // [rel][si*10+ci][j]: (se+ce) @ W1[rel]
__device__ float g_tabPos[PO3];                        // [rel][pi][j]:      pe @ W1[rel]
__device__ float g_rootSC[RSC];                        // (se+ce) @ root1
__device__ float g_rootPos[RPO];                       // pe @ root1
__device__ float g_Btf[256 * 64];                      // [root2; W2_r] pre-rounded to tf32

__device__ __forceinline__ void red_add_v2(float* p, float a, float b) {
    asm volatile("red.global.add.v2.f32 [%0], {%1,%2};"
                 :: "l"(p), "f"(a), "f"(b) : "memory");
}

#define MMA_TF32(C, A, B) \
    asm("mma.sync.aligned.m16n8k8.row.col.f32.tf32.tf32.f32 " \
        "{%0,%1,%2,%3}, {%4,%5,%6,%7}, {%8,%9}, {%0,%1,%2,%3};" \
        : "+f"((C)[0]), "+f"((C)[1]), "+f"((C)[2]), "+f"((C)[3]) \
        : "r"((A)[0]), "r"((A)[1]), "r"((A)[2]), "r"((A)[3]), \
          "r"((B)[0]), "r"((B)[1]))

// ---------------- kernels ----------------
// Fused prep: per-(dst,rel) edge counts + packed ids + weight tables + tf32 B.
__global__ void k_prep(const int* __restrict__ ei, const int* __restrict__ et, int E,
                       const int* __restrict__ sid, const int* __restrict__ cid,
                       const int* __restrict__ pid, int N,
                       const float* __restrict__ se, const float* __restrict__ ce,
                       const float* __restrict__ pe, const float* __restrict__ W1,
                       const float* __restrict__ root1,
                       const float* __restrict__ root2, const float* __restrict__ W2) {
    int t = blockIdx.x * blockDim.x + threadIdx.x;
    if (t < E) atomicAdd(&g_cnt[ei[E + t] * RREL + et[t]], 1);
    if (t < N) g_pids[t] = (unsigned)(sid[t] * 10 + cid[t]) | ((unsigned)pid[t] << 9);
    if (t < 256 * 64) {
        int kk = t >> 6, c = t & 63;
        float w;
        if (kk < 64) w = root2[kk * HIDD + c];
        else {
            int kr = kk - 64;
            w = W2[((size_t)(kr >> 6) * HIDD + (kr & 63)) * HIDD + c];
        }
        unsigned u;
        asm("cvt.rna.tf32.f32 %0, %1;" : "=r"(u) : "f"(w));
        g_Btf[t] = __uint_as_float(u);
    }
    if (t < SC3 + PO3 + RSC + RPO) {
        if (t < SC3) {
            int rel = t / (TSC * HIDD), rem = t % (TSC * HIDD);
            int row = rem / HIDD, j = rem % HIDD;
            int si = row / 10, ci = row % 10;
            const float* w = W1 + (size_t)rel * EMBD * HIDD + j;
            float s = 0.f;
            #pragma unroll
            for (int k = 0; k < EMBD; k++)
                s += (se[si * EMBD + k] + ce[ci * EMBD + k]) * w[k * HIDD];
            g_tabSC[t] = s;
        } else if (t < SC3 + PO3) {
            int u = t - SC3;
            int rel = u / (TPOS * HIDD), rem = u % (TPOS * HIDD);
            int row = rem / HIDD, j = rem % HIDD;
            const float* w = W1 + (size_t)rel * EMBD * HIDD + j;
            float s = 0.f;
            #pragma unroll
            for (int k = 0; k < EMBD; k++) s += pe[row * EMBD + k] * w[k * HIDD];
            g_tabPos[u] = s;
        } else if (t < SC3 + PO3 + RSC) {
            int u = t - SC3 - PO3;
            int row = u / HIDD, j = u % HIDD;
            int si = row / 10, ci = row % 10;
            float s = 0.f;
            #pragma unroll
            for (int k = 0; k < EMBD; k++)
                s += (se[si * EMBD + k] + ce[ci * EMBD + k]) * root1[k * HIDD + j];
            g_rootSC[u] = s;
        } else {
            int u = t - SC3 - PO3 - RSC;
            int row = u / HIDD, j = u % HIDD;
            float s = 0.f;
            #pragma unroll
            for (int k = 0; k < EMBD; k++) s += pe[row * EMBD + k] * root1[k * HIDD + j];
            g_rootPos[u] = s;
        }
    }
}

// Per node: inv weights, graph counts, rel-sorted CSR segment boundaries.
// Re-zeroes g_cnt (self-cleaning).
__global__ void k_base(const int* __restrict__ batch, int N) {
    int t    = blockIdx.x * blockDim.x + threadIdx.x;
    int lane = threadIdx.x & 31;
    int deg  = 0, c0 = 0, c1 = 0;
    if (t < N) {
        c0 = g_cnt[3 * t]; c1 = g_cnt[3 * t + 1];
        int c2 = g_cnt[3 * t + 2];
        g_cnt[3 * t] = 0; g_cnt[3 * t + 1] = 0; g_cnt[3 * t + 2] = 0;
        deg = c0 + c1 + c2;
        g_inv[3 * t + 0] = 1.0f / (float)(c0 > 0 ? c0 : 1);
        g_inv[3 * t + 1] = 1.0f / (float)(c1 > 0 ? c1 : 1);
        g_inv[3 * t + 2] = 1.0f / (float)(c2 > 0 ? c2 : 1);
        atomicAdd(&g_gcnt[batch[t]], 1);
    }
    int incl = deg;
    #pragma unroll
    for (int off = 1; off < 32; off <<= 1) {
        int v = __shfl_up_sync(0xffffffffu, incl, off);
        if (lane >= off) incl += v;
    }
    int total = __shfl_sync(0xffffffffu, incl, 31);
    int base = 0;
    if (lane == 31 && total > 0) base = atomicAdd(&g_ctr[0], total);
    base = __shfl_sync(0xffffffffu, base, 31);
    if (t < N) {
        int b = base + incl - deg;
        int4 v; v.x = b; v.y = b + c0; v.z = b + c0 + c1; v.w = b + deg;
        *(int4*)&g_base4[4 * t] = v;
    }
}

// CSR placement into per-(dst,rel) segments; SINGLE u64 scattered store.
// Resets g_ctr.
__global__ void k_place(const int* __restrict__ ei, const int* __restrict__ et, int E) {
    int e = blockIdx.x * blockDim.x + threadIdx.x;
    if (e == 0) g_ctr[0] = 0;
    if (e >= E) return;
    int s = ei[e], d = ei[E + e], r = et[e];
    int pos = g_base4[4 * d + r] + atomicAdd(&g_fill[3 * d + r], 1);
    g_edge[pos] = (unsigned long long)(unsigned)s
                | ((unsigned long long)g_pids[s] << 32);
}

// Layer 1: HALF-warp per dst node (16 lanes x float4); ONE fused loop over the
// whole adjacency, rel recovered by comparing e against segment boundaries.
// Per edge: pid (pipelined, hi word), 2 table gathers, weighted FMA. Merged outinit.
__global__ __launch_bounds__(256, 6) void k_agg1(
        const float* __restrict__ b1,
        const float* __restrict__ lin_b, float* __restrict__ out,
        int G, int N) {
    int gt = blockIdx.x * blockDim.x + threadIdx.x;
    if (gt < G) {
        out[2 * gt + 0] = lin_b[0];
        out[2 * gt + 1] = lin_b[1];
        int c = g_gcnt[gt];
        g_ginv[gt] = 1.0f / (float)(c > 0 ? c : 1);
        g_gcnt[gt] = 0;
    }
    int lane = threadIdx.x & 31;
    int half = lane >> 4, l = lane & 15;
    int d = blockIdx.x * 16 + (threadIdx.x >> 5) * 2 + half;
    if (d >= N) return;
    int j = l * 4;
    int4 b = *(const int4*)&g_base4[4 * d];
    float inv0 = g_inv[3 * d], inv1 = g_inv[3 * d + 1], inv2 = g_inv[3 * d + 2];
    float4 acc = {0.f, 0.f, 0.f, 0.f};
    const uint2* ge = (const uint2*)g_edge;
    unsigned pn = (b.x < b.w) ? ge[b.x].y : 0u;
    for (int e = b.x; e < b.w; e++) {
        unsigned p = pn;
        if (e + 1 < b.w) pn = ge[e + 1].y;
        int rel = (e >= b.y) + (e >= b.z);
        float w = (e < b.y) ? inv0 : ((e < b.z) ? inv1 : inv2);
        int scx = p & 511, pp = (int)(p >> 9);
        float4 m0 = *(const float4*)&g_tabSC[rel * (TSC * HIDD) + scx * HIDD + j];
        float4 m1 = *(const float4*)&g_tabPos[rel * (TPOS * HIDD) + pp * HIDD + j];
        acc.x += w * (m0.x + m1.x);
        acc.y += w * (m0.y + m1.y);
        acc.z += w * (m0.z + m1.z);
        acc.w += w * (m0.w + m1.w);
    }
    unsigned pd = g_pids[d];
    int scx = pd & 511, pp = (int)(pd >> 9);
    float4 r0 = *(const float4*)&g_rootSC[scx * HIDD + j];
    float4 r1 = *(const float4*)&g_rootPos[pp * HIDD + j];
    float4 bv = *(const float4*)&b1[j];
    float4 o;
    o.x = fmaxf(acc.x + r0.x + r1.x + bv.x, 0.f);
    o.y = fmaxf(acc.y + r0.y + r1.y + bv.y, 0.f);
    o.z = fmaxf(acc.z + r0.z + r1.z + bv.z, 0.f);
    o.w = fmaxf(acc.w + r0.w + r1.w + bv.w, 0.f);
    *(float4*)&g_h1[(size_t)d * HIDD + j] = o;
}

// Layer 2 aggregation: HALF-warp per node, rel-sorted segment sub-loops (the
// round-14 measured-best form), pipelined src stream (lo word). Resets g_fill.
__global__ __launch_bounds__(256, 6) void k_agg2(int N) {
    int lane = threadIdx.x & 31;
    int half = lane >> 4, l = lane & 15;
    int d = blockIdx.x * 16 + (threadIdx.x >> 5) * 2 + half;
    if (d >= N) return;
    int j = l * 4;
    int4 b = *(const int4*)&g_base4[4 * d];
    if (l < 3) g_fill[3 * d + l] = 0;
    const uint2* ge = (const uint2*)g_edge;
    float* dst = g_agg + (size_t)d * (RREL * HIDD);
    #pragma unroll
    for (int r = 0; r < 3; r++) {
        int lo = (r == 0) ? b.x : ((r == 1) ? b.y : b.z);
        int hi = (r == 0) ? b.y : ((r == 1) ? b.z : b.w);
        float invr = g_inv[3 * d + r];
        float4 s = {0.f, 0.f, 0.f, 0.f};
        unsigned sn = (lo < hi) ? ge[lo].x : 0u;
        for (int e = lo; e < hi; e++) {
            unsigned src = sn;
            if (e + 1 < hi) sn = ge[e + 1].x;
            float4 v = *(const float4*)&g_h1[(size_t)src * HIDD + j];
            s.x += v.x; s.y += v.y; s.z += v.z; s.w += v.w;
        }
        float4 o;
        o.x = s.x * invr; o.y = s.y * invr; o.z = s.z * invr; o.w = s.w * invr;
        *(float4*)&dst[r * HIDD + j] = o;
    }
}

// Layer-2 GEMM via single tf32 mma.sync + fused pooling head.
// Per CTA: 128 nodes x 64 cols, K=256 in 8 chunks of 32. 8 warps:
//   warp tile = 32 rows x 32 cols = 2 m-frags x 4 n-frags of m16n8k8.
#define AP  36   // Ah row stride
#define BQ  72   // Bs k-row stride
#define H2P 66
#define POOLSZ (128 * H2P)   // 8448 floats; staging needs 128*AP+32*BQ = 6912
__global__ __launch_bounds__(256, 4) void k_gemm_mma(
        const float* __restrict__ b2, const float* __restrict__ linW,
        const int* __restrict__ batch, float* __restrict__ out, int N) {
    __shared__ float pool[POOLSZ];                   // 33.8 KB
    float* Ah  = pool;
    float* Bs  = pool + 128 * AP;
    float* h2s = pool;                               // overlay after K loop

    int i0  = blockIdx.x * 128;
    int tid = threadIdx.x;
    int w   = tid >> 5, lane = tid & 31;
    int g   = lane >> 2, t4 = lane & 3;
    int rowbase = (w >> 1) * 32, colbase = (w & 1) * 32;

    float c[2][4][4];
    #pragma unroll
    for (int mt = 0; mt < 2; mt++)
        #pragma unroll
        for (int nt = 0; nt < 4; nt++)
            #pragma unroll
            for (int q = 0; q < 4; q++) c[mt][nt][q] = 0.f;

    for (int ph = 0; ph < 8; ph++) {
        __syncthreads();
        // ---- stage B chunk [32 x 64] (already tf32-rounded) ----
        #pragma unroll
        for (int t = 0; t < 8; t++) {
            int idx = tid + t * 256;
            int k = idx >> 6, cc = idx & 63;
            Bs[k * BQ + cc] = g_Btf[(ph * 32 + k) * 64 + cc];
        }
        // ---- stage A chunk [128 node x 32 k], tf32-rounded ----
        {
            int node = tid & 127, half = tid >> 7;    // half covers k 0..15 / 16..31
            int gi = i0 + node;
            float4 v[4];
            if (gi < N) {
                const float4* src;
                if (ph < 2) src = (const float4*)&g_h1[(size_t)gi * HIDD + ph * 32 + half * 16];
                else        src = (const float4*)&g_agg[(size_t)gi * (RREL * HIDD) + (ph - 2) * 32 + half * 16];
                #pragma unroll
                for (int q = 0; q < 4; q++) v[q] = src[q];
            } else {
                #pragma unroll
                for (int q = 0; q < 4; q++) v[q] = make_float4(0.f, 0.f, 0.f, 0.f);
            }
            #pragma unroll
            for (int q = 0; q < 4; q++) {
                float vals[4] = {v[q].x, v[q].y, v[q].z, v[q].w};
                #pragma unroll
                for (int e = 0; e < 4; e++) {
                    unsigned hu;
                    asm("cvt.rna.tf32.f32 %0, %1;" : "=r"(hu) : "f"(vals[e]));
                    Ah[node * AP + half * 16 + q * 4 + e] = __uint_as_float(hu);
                }
            }
        }
        __syncthreads();
        // ---- 4 k-steps of 8 ----
        #pragma unroll
        for (int ks = 0; ks < 4; ks++) {
            int k0 = ks * 8;
            unsigned ah[2][4], bf[4][2];
            #pragma unroll
            for (int mt = 0; mt < 2; mt++) {
                int r0 = rowbase + 16 * mt + g;
                ah[mt][0] = __float_as_uint(Ah[r0 * AP + k0 + t4]);
                ah[mt][1] = __float_as_uint(Ah[(r0 + 8) * AP + k0 + t4]);
                ah[mt][2] = __float_as_uint(Ah[r0 * AP + k0 + t4 + 4]);
                ah[mt][3] = __float_as_uint(Ah[(r0 + 8) * AP + k0 + t4 + 4]);
            }
            #pragma unroll
            for (int nt = 0; nt < 4; nt++) {
                int cc = colbase + 8 * nt + g;
                bf[nt][0] = __float_as_uint(Bs[(k0 + t4) * BQ + cc]);
                bf[nt][1] = __float_as_uint(Bs[(k0 + t4 + 4) * BQ + cc]);
            }
            #pragma unroll
            for (int mt = 0; mt < 2; mt++)
                #pragma unroll
                for (int nt = 0; nt < 4; nt++)
                    MMA_TF32(c[mt][nt], ah[mt], bf[nt]);
        }
    }
    __syncthreads();
    // ---- store h2 tile to smem (overlay) ----
    #pragma unroll
    for (int mt = 0; mt < 2; mt++)
        #pragma unroll
        for (int nt = 0; nt < 4; nt++) {
            int r0 = rowbase + 16 * mt + g;
            int cc = colbase + 8 * nt + 2 * t4;
            *(float2*)&h2s[r0 * H2P + cc]       = make_float2(c[mt][nt][0], c[mt][nt][1]);
            *(float2*)&h2s[(r0 + 8) * H2P + cc] = make_float2(c[mt][nt][2], c[mt][nt][3]);
        }
    __syncthreads();
    // ---- per-warp row reduction: rows 16w..16w+15 ----
    float2 bb = *(const float2*)&b2[2 * lane];
    float4 lw = *(const float4*)&linW[4 * lane];   // cols 2lane, 2lane+1 x outs {0,1}
    for (int rr = 0; rr < 16; rr++) {
        int row = w * 16 + rr;
        float2 v = *(const float2*)&h2s[row * H2P + 2 * lane];
        float v0 = fmaxf(v.x + bb.x, 0.f);
        float v1 = fmaxf(v.y + bb.y, 0.f);
        float s0 = v0 * lw.x + v1 * lw.z;
        float s1 = v0 * lw.y + v1 * lw.w;
        #pragma unroll
        for (int m = 16; m > 0; m >>= 1) {
            s0 += __shfl_xor_sync(0xffffffffu, s0, m);
            s1 += __shfl_xor_sync(0xffffffffu, s1, m);
        }
        int gi = i0 + row;
        if (lane == 0 && gi < N) {
            int b = batch[gi];
            float gw = g_ginv[b];
            red_add_v2(&out[2 * b], s0 * gw, s1 * gw);
        }
    }
}

// ---------------- launch ----------------
extern "C" void kernel_launch(void* const* d_in, const int* in_sizes, int n_in,
                              void* d_out, int out_size) {
    const int* sid = (const int*)d_in[0];
    const int* cid = (const int*)d_in[1];
    const int* pid = (const int*)d_in[2];
    const int* ei  = (const int*)d_in[3];
    const int* et  = (const int*)d_in[4];
    const int* bat = (const int*)d_in[5];
    int off = (in_sizes[6] == 1) ? 7 : 6;
    const float* se    = (const float*)d_in[off + 0];
    const float* ce    = (const float*)d_in[off + 1];
    const float* pe    = (const float*)d_in[off + 2];
    const float* W1    = (const float*)d_in[off + 3];
    const float* root1 = (const float*)d_in[off + 4];
    const float* b1    = (const float*)d_in[off + 5];
    const float* W2    = (const float*)d_in[off + 6];
    const float* root2 = (const float*)d_in[off + 7];
    const float* b2    = (const float*)d_in[off + 8];
    const float* linW  = (const float*)d_in[off + 9];
    const float* linb  = (const float*)d_in[off + 10];
    float* out = (float*)d_out;

    int N = in_sizes[0];
    int E = in_sizes[4];
    int G = out_size / 2;
    const int TB = 256;

    k_prep<<<(E + TB - 1) / TB, TB>>>(ei, et, E, sid, cid, pid, N,
                                      se, ce, pe, W1, root1, root2, W2);
    k_base<<<(N + TB - 1) / TB, TB>>>(bat, N);
    k_place<<<(E + TB - 1) / TB, TB>>>(ei, et, E);
    k_agg1<<<(N + 15) / 16, TB>>>(b1, linb, out, G, N);   // <- profiled slot (4th)
    k_agg2<<<(N + 15) / 16, TB>>>(N);
    k_gemm_mma<<<(N + 127) / 128, TB>>>(b2, linW, bat, out, N);
}